// round 13
// baseline (speedup 1.0000x reference)
#include <cuda_runtime.h>
#include <cuda_bf16.h>
#include <cuda_fp16.h>
#include <math.h>
#include <cstdint>

#define NN 100000
#define EE 1600000
#define DD 128
#define HH 4
#define NTILE 782           // ceil(NN/128)
#define PGRID 148           // persistent GEMM grid (1 CTA/SM)

// ---------------- device scratch (static globals: allocation-free rule) ----
__device__ __half g_h16[(size_t)NN * DD];          // fp16 h for agg gather
__device__ float  g_bf[DD];                        // Wg @ b1
__device__ uint4  g_Wfh[2048], g_Wfl[2048];        // Wf bf16 hi/lo, tile layout
__device__ uint4  g_W2h[2048], g_W2l[2048];        // W2 bf16 hi/lo, tile layout
__device__ uint4  g_xh[(size_t)NTILE * 2048];      // leaky(x) bf16 hi, tiles
__device__ uint4  g_xl[(size_t)NTILE * 2048];      // leaky(x) bf16 lo, tiles
__device__ uint4  g_ah[(size_t)NTILE * 2048];      // leaky(agg+bg) bf16 hi
__device__ uint4  g_al[(size_t)NTILE * 2048];      // leaky(agg+bg) bf16 lo
__device__ float  g_asrc[NN * HH];
__device__ float  g_adst[NN * HH];
__device__ int    g_cnt[NN];                       // degree (zeroed by agg)
__device__ int    g_off[NN + 1];
__device__ int    g_cur[NN];
__device__ int    g_csr_src[EE];

__device__ __forceinline__ float lrelu(float x, float s) {
    return x >= 0.f ? x : s * x;
}
__device__ __forceinline__ uint32_t smem_u32(const void* p) {
    uint32_t a;
    asm("{ .reg .u64 t; cvta.to.shared.u64 t, %1; cvt.u32.u64 %0, t; }"
        : "=r"(a) : "l"(p));
    return a;
}
__device__ __forceinline__ uint32_t pack_bf2(float a, float b) {
    __nv_bfloat162 t = __floats2bfloat162_rn(a, b);
    return *reinterpret_cast<uint32_t*>(&t);
}
__device__ __forceinline__ void cp16(uint32_t s, const void* g) {
    asm volatile("cp.async.cg.shared.global [%0], [%1], 16;"
                 :: "r"(s), "l"(g));
}
__device__ __forceinline__ void ldsm_x4(uint32_t& r0, uint32_t& r1,
                                        uint32_t& r2, uint32_t& r3, uint32_t a) {
    asm volatile("ldmatrix.sync.aligned.m8n8.x4.shared.b16 {%0,%1,%2,%3}, [%4];"
                 : "=r"(r0), "=r"(r1), "=r"(r2), "=r"(r3) : "r"(a));
}
__device__ __forceinline__ void ldsm_x2(uint32_t& r0, uint32_t& r1, uint32_t a) {
    asm volatile("ldmatrix.sync.aligned.m8n8.x2.shared.b16 {%0,%1}, [%2];"
                 : "=r"(r0), "=r"(r1) : "r"(a));
}
__device__ __forceinline__ void mma16816(float* d, const uint32_t* a,
                                         const uint32_t* b) {
    asm volatile("mma.sync.aligned.m16n8k16.row.col.f32.bf16.bf16.f32 "
                 "{%0,%1,%2,%3}, {%4,%5,%6,%7}, {%8,%9}, {%0,%1,%2,%3};"
                 : "+f"(d[0]), "+f"(d[1]), "+f"(d[2]), "+f"(d[3])
                 : "r"(a[0]), "r"(a[1]), "r"(a[2]), "r"(a[3]),
                   "r"(b[0]), "r"(b[1]));
}

// ---------------------------------------------------------------------------
// Setup grid (one kernel, disjoint block ranges):
//  [0, HBLK)                : dst-degree histogram
//  [HBLK, HBLK+64)          : Wf = Wg@W1 rows + bf16 split; bf = Wg@b1
//  [HBLK+64, HBLK+72)       : W2 bf16 split
//  [HBLK+72, HBLK+72+XBLK)  : leaky(x) -> bf16 hi/lo swizzled tiles
// Tile layout: row r (256B), granule g at r*256 + ((g^(r&7))<<4).
// ---------------------------------------------------------------------------
#define HBLK ((EE + 255) / 256)
#define XBLK ((NN * 16) / 256)
__global__ void __launch_bounds__(256) setup_kernel(
    const int* __restrict__ ei, const float* __restrict__ Wg,
    const float* __restrict__ W1, const float* __restrict__ b1,
    const float* __restrict__ W2, const float* __restrict__ x)
{
    if (blockIdx.x < HBLK) {
        int e = blockIdx.x * 256 + threadIdx.x;
        if (e < EE) atomicAdd(&g_cnt[ei[EE + e]], 1);
    } else if (blockIdx.x < HBLK + 64) {
        int i = (blockIdx.x - HBLK) * 2 + (threadIdx.x >> 7);
        int k = threadIdx.x & 127;
        float acc = 0.f, accb = 0.f;
#pragma unroll 8
        for (int j = 0; j < DD; j++) {
            float w = Wg[i * DD + j];
            acc = fmaf(w, W1[j * DD + k], acc);
            accb = fmaf(w, b1[j], accb);
        }
        float h = __bfloat162float(__float2bfloat16(acc));
        int off = i * 256 + ((((k >> 3) ^ (i & 7))) << 4) + (k & 7) * 2;
        *(__nv_bfloat16*)((char*)g_Wfh + off) = __float2bfloat16(acc);
        *(__nv_bfloat16*)((char*)g_Wfl + off) = __float2bfloat16(acc - h);
        if (k == 0) g_bf[i] = accb;
    } else if (blockIdx.x < HBLK + 72) {
        int gidx = (blockIdx.x - HBLK - 64) * 256 + threadIdx.x;
        int r = gidx >> 4, g = gidx & 15;
        float4 u0 = *(const float4*)(W2 + (size_t)r * DD + g * 8);
        float4 u1 = *(const float4*)(W2 + (size_t)r * DD + g * 8 + 4);
        float v[8] = {u0.x, u0.y, u0.z, u0.w, u1.x, u1.y, u1.z, u1.w};
        uint32_t hi[4], lo[4];
#pragma unroll
        for (int p = 0; p < 4; p++) {
            float a0 = v[2 * p], a1 = v[2 * p + 1];
            float h0 = __bfloat162float(__float2bfloat16(a0));
            float h1 = __bfloat162float(__float2bfloat16(a1));
            hi[p] = pack_bf2(h0, h1);
            lo[p] = pack_bf2(a0 - h0, a1 - h1);
        }
        int off = r * 256 + (((g ^ (r & 7))) << 4);
        *(uint4*)((char*)g_W2h + off) = make_uint4(hi[0], hi[1], hi[2], hi[3]);
        *(uint4*)((char*)g_W2l + off) = make_uint4(lo[0], lo[1], lo[2], lo[3]);
    } else {
        int gidx = (blockIdx.x - HBLK - 72) * 256 + threadIdx.x;  // < NN*16
        int r = gidx >> 4, g = gidx & 15;
        float4 u0 = *(const float4*)(x + (size_t)r * DD + g * 8);
        float4 u1 = *(const float4*)(x + (size_t)r * DD + g * 8 + 4);
        float v[8] = {u0.x, u0.y, u0.z, u0.w, u1.x, u1.y, u1.z, u1.w};
#pragma unroll
        for (int i = 0; i < 8; i++) v[i] = lrelu(v[i], 0.01f);
        uint32_t hi[4], lo[4];
#pragma unroll
        for (int p = 0; p < 4; p++) {
            float a0 = v[2 * p], a1 = v[2 * p + 1];
            float h0 = __bfloat162float(__float2bfloat16(a0));
            float h1 = __bfloat162float(__float2bfloat16(a1));
            hi[p] = pack_bf2(h0, h1);
            lo[p] = pack_bf2(a0 - h0, a1 - h1);
        }
        size_t off = (size_t)(r >> 7) * 32768 + (r & 127) * 256
                   + ((g ^ (r & 7)) << 4);
        *(uint4*)((char*)g_xh + off) = make_uint4(hi[0], hi[1], hi[2], hi[3]);
        *(uint4*)((char*)g_xl + off) = make_uint4(lo[0], lo[1], lo[2], lo[3]);
    }
}

// ---------------------------------------------------------------------------
// Persistent HMMA GEMM (148 blocks x 512 thr): each block owns ~5-6 row
// tiles. W staged ONCE per block; A tiles double-buffered with cp.async
// groups so tile i+1 streams in while tile i computes.
// smem: A0 hi/lo (64K) | A1 hi/lo (64K) | W hi/lo (64K) | sp (8K) | sd (8K)
//   = 208 KB total (previous round under-sized this by 8K -> smem OOB crash).
// D = AhWh + AhWl + AlWh, fp32 accumulate.
// ATTN: CSR-scatter prologue overlaps W/A0 stream-in; epilogue writes fp16 h
// mirror + attention scores. else: fp32 out + bias.
// ---------------------------------------------------------------------------
template <bool ATTN>
__global__ void __launch_bounds__(512, 1) gemm_kernel(
    const uint4* __restrict__ Ah, const uint4* __restrict__ Al,
    const uint4* __restrict__ Wh, const uint4* __restrict__ Wl,
    const float* __restrict__ bias,
    const float* __restrict__ attS, const float* __restrict__ attD,
    float* __restrict__ out, int M, const int* __restrict__ ei)
{
    extern __shared__ char smem[];
    const int tid = threadIdx.x;
    const uint32_t sb = smem_u32(smem);
    const uint32_t sW = sb + 131072;           // Wh @ +0, Wl @ +32768
    float* sp = (float*)(smem + 196608);       // [128][16]  (8 KB)
    float* sd = sp + 128 * 16;                 // [128][16]  (8 KB)

    // ---- stage W once (group 0) ----
#pragma unroll
    for (int it = 0; it < 4; it++) {
        int idx = tid + it * 512;
        cp16(sW + idx * 16, Wh + idx);
        cp16(sW + 32768 + idx * 16, Wl + idx);
    }
    asm volatile("cp.async.commit_group;");

    int t = blockIdx.x;
    // ---- stage first A tile into buf 0 (group 1) ----
#pragma unroll
    for (int it = 0; it < 4; it++) {
        int idx = tid + it * 512;
        cp16(sb + idx * 16, Ah + (size_t)t * 2048 + idx);
        cp16(sb + 32768 + idx * 16, Al + (size_t)t * 2048 + idx);
    }
    asm volatile("cp.async.commit_group;");

    if (ATTN) {  // CSR scatter overlaps the stream-in
        const int EPB = (EE + PGRID - 1) / PGRID;
        int e0 = blockIdx.x * EPB;
        int e1 = e0 + EPB < EE ? e0 + EPB : EE;
        for (int e = e0 + tid; e < e1; e += 512) {
            int src = ei[e];
            int dst = ei[EE + e];
            int pos = atomicAdd(&g_cur[dst], 1);
            g_csr_src[pos] = src;
        }
    }

    const int wid = tid >> 5, lane = tid & 31;
    const int wm = (wid >> 2) * 32, wn = (wid & 3) * 32;
    const int subA = lane >> 3;
    const int rA = (lane & 7) | ((subA & 1) << 3);
    const int gA = subA >> 1;
    const int rB = lane & 7;
    const int gB = (lane >> 3) & 1;
    const int q = lane >> 2, c2 = (lane & 3) * 2;

    float bj0[4], bj1[4], as0[4], as1[4], ad0[4], ad1[4];
#pragma unroll
    for (int nt = 0; nt < 4; nt++) {
        int col = wn + nt * 8 + c2;
        bj0[nt] = bias[col];
        bj1[nt] = bias[col + 1];
        if (ATTN) {
            as0[nt] = attS[col]; as1[nt] = attS[col + 1];
            ad0[nt] = attD[col]; ad1[nt] = attD[col + 1];
        }
    }

    int cur = 0;
    while (t < NTILE) {
        int tn = t + PGRID;
        if (tn < NTILE) {  // prefetch next tile into the other buffer
            uint32_t dst = sb + (1 - cur) * 65536;
#pragma unroll
            for (int it = 0; it < 4; it++) {
                int idx = tid + it * 512;
                cp16(dst + idx * 16, Ah + (size_t)tn * 2048 + idx);
                cp16(dst + 32768 + idx * 16, Al + (size_t)tn * 2048 + idx);
            }
            asm volatile("cp.async.commit_group;");
            asm volatile("cp.async.wait_group 1;");
        } else {
            asm volatile("cp.async.wait_group 0;");
        }
        __syncthreads();

        const uint32_t sA = sb + cur * 65536;
        const int rowBase = t * 128;

        float D[2][4][4];
#pragma unroll
        for (int mt = 0; mt < 2; mt++)
#pragma unroll
            for (int nt = 0; nt < 4; nt++)
#pragma unroll
                for (int k = 0; k < 4; k++) D[mt][nt][k] = 0.f;

#pragma unroll
        for (int p = 0; p < 3; p++) {
            uint32_t aBase = sA + ((p == 2) ? 32768 : 0);
            uint32_t bBase = sW + ((p == 1) ? 32768 : 0);
#pragma unroll
            for (int ks = 0; ks < 8; ks++) {
                uint32_t a[2][4], b[4][2];
#pragma unroll
                for (int mt = 0; mt < 2; mt++) {
                    int r = wm + mt * 16 + rA;
                    int g = 2 * ks + gA;
                    ldsm_x4(a[mt][0], a[mt][1], a[mt][2], a[mt][3],
                            aBase + r * 256 + ((g ^ (r & 7)) << 4));
                }
#pragma unroll
                for (int nt = 0; nt < 4; nt++) {
                    int r = wn + nt * 8 + rB;
                    int g = 2 * ks + gB;
                    ldsm_x2(b[nt][0], b[nt][1],
                            bBase + r * 256 + ((g ^ (r & 7)) << 4));
                }
#pragma unroll
                for (int mt = 0; mt < 2; mt++)
#pragma unroll
                    for (int nt = 0; nt < 4; nt++)
                        mma16816(D[mt][nt], a[mt], b[nt]);
            }
        }

        // ---- epilogue ----
#pragma unroll
        for (int mt = 0; mt < 2; mt++) {
#pragma unroll
            for (int half = 0; half < 2; half++) {
                int rl = wm + mt * 16 + q + half * 8;
                int row = rowBase + rl;
                bool ok = row < M;
#pragma unroll
                for (int nt = 0; nt < 4; nt++) {
                    int col = wn + nt * 8 + c2;
                    float v0 = D[mt][nt][half * 2] + bj0[nt];
                    float v1 = D[mt][nt][half * 2 + 1] + bj1[nt];
                    if (ATTN) {
                        if (ok) {
                            *(__half2*)(g_h16 + (size_t)row * DD + col) =
                                __floats2half2_rn(v0, v1);
                        }
                        float ps = v0 * as0[nt] + v1 * as1[nt];
                        float pd = v0 * ad0[nt] + v1 * ad1[nt];
                        ps += __shfl_xor_sync(0xffffffffu, ps, 1);
                        ps += __shfl_xor_sync(0xffffffffu, ps, 2);
                        pd += __shfl_xor_sync(0xffffffffu, pd, 1);
                        pd += __shfl_xor_sync(0xffffffffu, pd, 2);
                        if ((lane & 3) == 0) {
                            sp[rl * 16 + (wid & 3) * 4 + nt] = ps;
                            sd[rl * 16 + (wid & 3) * 4 + nt] = pd;
                        }
                    } else if (ok) {
                        *(float2*)(out + (size_t)row * DD + col) =
                            make_float2(v0, v1);
                    }
                }
            }
        }
        if (ATTN) {
            __syncthreads();
            if (tid < 128) {
                int row = rowBase + tid;
                if (row < M) {
#pragma unroll
                    for (int h = 0; h < 4; h++) {
                        float s = sp[tid * 16 + h * 4 + 0] + sp[tid * 16 + h * 4 + 1]
                                + sp[tid * 16 + h * 4 + 2] + sp[tid * 16 + h * 4 + 3];
                        float d = sd[tid * 16 + h * 4 + 0] + sd[tid * 16 + h * 4 + 1]
                                + sd[tid * 16 + h * 4 + 2] + sd[tid * 16 + h * 4 + 3];
                        g_asrc[row * HH + h] = s;
                        g_adst[row * HH + h] = d;
                    }
                }
            }
        }
        __syncthreads();  // all warps done with buf(cur) before it is refilled
        t = tn;
        cur ^= 1;
    }
}

// -------------------------- CSR scan + cursor copy ------------------------
__global__ void __launch_bounds__(1024) scan_kernel() {
    __shared__ int ssum[1024];
    const int t = threadIdx.x;
    const int CH = (NN + 1023) / 1024;
    const int base = t * CH;

    int s = 0;
#pragma unroll 4
    for (int i = 0; i < CH; i++) {
        int idx = base + i;
        if (idx < NN) s += g_cnt[idx];
    }
    ssum[t] = s;
    __syncthreads();
    for (int off = 1; off < 1024; off <<= 1) {
        int v = ssum[t];
        int add = (t >= off) ? ssum[t - off] : 0;
        __syncthreads();
        ssum[t] = v + add;
        __syncthreads();
    }
    int run = ssum[t] - s;
    for (int i = 0; i < CH; i++) {
        int idx = base + i;
        if (idx < NN) {
            g_off[idx] = run;
            run += g_cnt[idx];
        }
    }
    if (t == 1023) g_off[NN] = EE;
}

__global__ void __launch_bounds__(256) cur_copy_kernel() {
    int idx = blockIdx.x * 256 + threadIdx.x;
    if (idx < NN) g_cur[idx] = g_off[idx];
}

// ---------------------------------------------------------------------------
// Fused softmax + aggregation: warp per dst; fp16 gathers. Applies +bias_g
// and leaky, writes bf16 hi/lo directly into gemm<0>'s swizzled tile layout.
// Zeroes g_cnt for next call.
// ---------------------------------------------------------------------------
__global__ void __launch_bounds__(256) agg_kernel(const float* __restrict__ bg) {
    int warp = (blockIdx.x * blockDim.x + threadIdx.x) >> 5;
    int lane = threadIdx.x & 31;
    if (warp >= NN) return;
    const int d = warp;
    const int head = lane >> 3;
    const int ph = lane & 3;
    const int pe = lane >> 2;
    const int beg = g_off[d], end = g_off[d + 1];
    const float adst_ph = g_adst[d * HH + ph];
    const float4 bgl = *(const float4*)(bg + lane * 4);

    if (lane == 0) g_cnt[d] = 0;

    float4 acc = make_float4(0.f, 0.f, 0.f, 0.f);
    float den = 0.f;

    int base = beg;
    for (; base + 8 <= end; base += 8) {
        int srcl = g_csr_src[base + pe];
        float s = g_asrc[srcl * HH + ph] + adst_ph;
        float exv = __expf(lrelu(s, 0.2f));
#pragma unroll
        for (int j = 0; j < 8; j++) {
            float ex = __shfl_sync(0xffffffffu, exv, j * 4 + head);
            int sj = __shfl_sync(0xffffffffu, srcl, j * 4 + head);
            uint2 u = *(const uint2*)(g_h16 + (size_t)sj * DD + lane * 4);
            float2 f0 = __half22float2(*(__half2*)&u.x);
            float2 f1 = __half22float2(*(__half2*)&u.y);
            acc.x = fmaf(ex, f0.x, acc.x);
            acc.y = fmaf(ex, f0.y, acc.y);
            acc.z = fmaf(ex, f1.x, acc.z);
            acc.w = fmaf(ex, f1.y, acc.w);
            den += ex;
        }
    }
    if (base < end) {
        int eidx = base + pe;
        int srcl = 0;
        float exv = 0.f;
        if (eidx < end) {
            srcl = g_csr_src[eidx];
            float s = g_asrc[srcl * HH + ph] + adst_ph;
            exv = __expf(lrelu(s, 0.2f));
        }
        int nrem = end - base;
#pragma unroll
        for (int j = 0; j < 8; j++) {
            if (j >= nrem) break;
            float ex = __shfl_sync(0xffffffffu, exv, j * 4 + head);
            int sj = __shfl_sync(0xffffffffu, srcl, j * 4 + head);
            uint2 u = *(const uint2*)(g_h16 + (size_t)sj * DD + lane * 4);
            float2 f0 = __half22float2(*(__half2*)&u.x);
            float2 f1 = __half22float2(*(__half2*)&u.y);
            acc.x = fmaf(ex, f0.x, acc.x);
            acc.y = fmaf(ex, f0.y, acc.y);
            acc.z = fmaf(ex, f1.x, acc.z);
            acc.w = fmaf(ex, f1.y, acc.w);
            den += ex;
        }
    }
    float inv = 1.f / (den + 1e-16f);
    float v[4] = {lrelu(acc.x * inv + bgl.x, 0.01f),
                  lrelu(acc.y * inv + bgl.y, 0.01f),
                  lrelu(acc.z * inv + bgl.z, 0.01f),
                  lrelu(acc.w * inv + bgl.w, 0.01f)};
    float h0 = __bfloat162float(__float2bfloat16(v[0]));
    float h1 = __bfloat162float(__float2bfloat16(v[1]));
    float h2 = __bfloat162float(__float2bfloat16(v[2]));
    float h3 = __bfloat162float(__float2bfloat16(v[3]));
    uint2 hi = make_uint2(pack_bf2(h0, h1), pack_bf2(h2, h3));
    uint2 lo = make_uint2(pack_bf2(v[0] - h0, v[1] - h1),
                          pack_bf2(v[2] - h2, v[3] - h3));
    size_t off = (size_t)(d >> 7) * 32768 + (d & 127) * 256
               + (((lane >> 1) ^ (d & 7)) << 4) + (lane & 1) * 8;
    *(uint2*)((char*)g_ah + off) = hi;
    *(uint2*)((char*)g_al + off) = lo;
}

// ---------------------------------------------------------------------------
extern "C" void kernel_launch(void* const* d_in, const int* in_sizes, int n_in,
                              void* d_out, int out_size) {
    const float* x       = (const float*)d_in[0];
    const int*   ei      = (const int*)d_in[1];
    // d_in[2] = edge_type (unused by forward)
    const float* W1      = (const float*)d_in[3];
    const float* b1      = (const float*)d_in[4];
    const float* Wg      = (const float*)d_in[5];
    const float* att_src = (const float*)d_in[6];
    const float* att_dst = (const float*)d_in[7];
    const float* bias_g  = (const float*)d_in[8];
    const float* W2      = (const float*)d_in[9];
    const float* b2      = (const float*)d_in[10];
    float* out = (float*)d_out;

    float *pbf;
    uint4 *pWfh, *pWfl, *pW2h, *pW2l, *pxh, *pxl, *pah, *pal;
    cudaGetSymbolAddress((void**)&pbf, g_bf);
    cudaGetSymbolAddress((void**)&pWfh, g_Wfh);
    cudaGetSymbolAddress((void**)&pWfl, g_Wfl);
    cudaGetSymbolAddress((void**)&pW2h, g_W2h);
    cudaGetSymbolAddress((void**)&pW2l, g_W2l);
    cudaGetSymbolAddress((void**)&pxh, g_xh);
    cudaGetSymbolAddress((void**)&pxl, g_xl);
    cudaGetSymbolAddress((void**)&pah, g_ah);
    cudaGetSymbolAddress((void**)&pal, g_al);

    const int SMEM = 208 * 1024;  // A0(64K) A1(64K) W(64K) sp(8K) sd(8K)
    cudaFuncSetAttribute(gemm_kernel<true>,
                         cudaFuncAttributeMaxDynamicSharedMemorySize, SMEM);
    cudaFuncSetAttribute(gemm_kernel<false>,
                         cudaFuncAttributeMaxDynamicSharedMemorySize, SMEM);

    // 1: histogram + Wf/bf + W2 split + x split (fused grid)
    setup_kernel<<<HBLK + 72 + XBLK, 256>>>(ei, Wg, W1, b1, W2, x);
    // 2: CSR offsets
    scan_kernel<<<1, 1024>>>();
    // 3: cursor copy
    cur_copy_kernel<<<(NN + 255) / 256, 256>>>();
    // 4: scatter + h16/attn GEMM, persistent + double-buffered (<- profiled)
    gemm_kernel<true><<<PGRID, 512, SMEM>>>(pxh, pxl, pWfh, pWfl, pbf,
                                            att_src, att_dst, nullptr, NN, ei);
    // 5: fused softmax + aggregation (writes pre-split bf16 tiles)
    agg_kernel<<<(NN * 32 + 255) / 256, 256>>>(bias_g);
    // 6: out = agg16 @ W2^T + b2, persistent + double-buffered
    gemm_kernel<false><<<PGRID, 512, SMEM>>>(pah, pal, pW2h, pW2l, b2,
                                             nullptr, nullptr, out, NN, nullptr);
}

// round 14
// speedup vs baseline: 1.7185x; 1.7185x over previous
#include <cuda_runtime.h>
#include <cuda_bf16.h>
#include <cuda_fp16.h>
#include <math.h>
#include <cstdint>

#define NN 100000
#define EE 1600000
#define DD 128
#define HH 4
#define NTILE 782           // ceil(NN/128)   (128-row tile count, storage)
#define NT64 1563           // ceil(NN/64)    (64-row GEMM tile count)

// ---------------- device scratch (static globals: allocation-free rule) ----
__device__ __half g_h16[(size_t)NN * DD];          // fp16 h for agg gather
__device__ float  g_bf[DD];                        // Wg @ b1
__device__ uint4  g_Wfh[2048], g_Wfl[2048];        // Wf bf16 hi/lo, tile layout
__device__ uint4  g_W2h[2048], g_W2l[2048];        // W2 bf16 hi/lo, tile layout
__device__ uint4  g_xh[(size_t)NTILE * 2048];      // leaky(x) bf16 hi (row r at byte r*256)
__device__ uint4  g_xl[(size_t)NTILE * 2048];      // leaky(x) bf16 lo
__device__ uint4  g_ah[(size_t)NTILE * 2048];      // leaky(agg+bg) bf16 hi
__device__ uint4  g_al[(size_t)NTILE * 2048];      // leaky(agg+bg) bf16 lo
__device__ float  g_asrc[NN * HH];
__device__ float  g_adst[NN * HH];
__device__ int    g_cnt[NN];                       // degree (zeroed by agg)
__device__ int    g_off[NN + 1];
__device__ int    g_cur[NN];
__device__ int    g_csr_src[EE];

__device__ __forceinline__ float lrelu(float x, float s) {
    return x >= 0.f ? x : s * x;
}
__device__ __forceinline__ uint32_t smem_u32(const void* p) {
    uint32_t a;
    asm("{ .reg .u64 t; cvta.to.shared.u64 t, %1; cvt.u32.u64 %0, t; }"
        : "=r"(a) : "l"(p));
    return a;
}
__device__ __forceinline__ uint32_t pack_bf2(float a, float b) {
    __nv_bfloat162 t = __floats2bfloat162_rn(a, b);
    return *reinterpret_cast<uint32_t*>(&t);
}
__device__ __forceinline__ void cp16(uint32_t s, const void* g) {
    asm volatile("cp.async.cg.shared.global [%0], [%1], 16;"
                 :: "r"(s), "l"(g));
}
__device__ __forceinline__ void ldsm_x4(uint32_t& r0, uint32_t& r1,
                                        uint32_t& r2, uint32_t& r3, uint32_t a) {
    asm volatile("ldmatrix.sync.aligned.m8n8.x4.shared.b16 {%0,%1,%2,%3}, [%4];"
                 : "=r"(r0), "=r"(r1), "=r"(r2), "=r"(r3) : "r"(a));
}
__device__ __forceinline__ void ldsm_x2(uint32_t& r0, uint32_t& r1, uint32_t a) {
    asm volatile("ldmatrix.sync.aligned.m8n8.x2.shared.b16 {%0,%1}, [%2];"
                 : "=r"(r0), "=r"(r1) : "r"(a));
}
__device__ __forceinline__ void mma16816(float* d, const uint32_t* a,
                                         const uint32_t* b) {
    asm volatile("mma.sync.aligned.m16n8k16.row.col.f32.bf16.bf16.f32 "
                 "{%0,%1,%2,%3}, {%4,%5,%6,%7}, {%8,%9}, {%0,%1,%2,%3};"
                 : "+f"(d[0]), "+f"(d[1]), "+f"(d[2]), "+f"(d[3])
                 : "r"(a[0]), "r"(a[1]), "r"(a[2]), "r"(a[3]),
                   "r"(b[0]), "r"(b[1]));
}

// ---------------------------------------------------------------------------
// Setup grid (one kernel, disjoint block ranges):
//  [0, HBLK)                : dst-degree histogram
//  [HBLK, HBLK+64)          : Wf = Wg@W1 rows + bf16 split; bf = Wg@b1
//  [HBLK+64, HBLK+72)       : W2 bf16 split
//  [HBLK+72, HBLK+72+XBLK)  : leaky(x) -> bf16 hi/lo swizzled tiles
// Tile layout: row r (256B) at byte r*256; granule g at ((g^(r&7))<<4).
// ---------------------------------------------------------------------------
#define HBLK ((EE + 255) / 256)
#define XBLK ((NN * 16) / 256)
__global__ void __launch_bounds__(256) setup_kernel(
    const int* __restrict__ ei, const float* __restrict__ Wg,
    const float* __restrict__ W1, const float* __restrict__ b1,
    const float* __restrict__ W2, const float* __restrict__ x)
{
    if (blockIdx.x < HBLK) {
        int e = blockIdx.x * 256 + threadIdx.x;
        if (e < EE) atomicAdd(&g_cnt[ei[EE + e]], 1);
    } else if (blockIdx.x < HBLK + 64) {
        int i = (blockIdx.x - HBLK) * 2 + (threadIdx.x >> 7);
        int k = threadIdx.x & 127;
        float acc = 0.f, accb = 0.f;
#pragma unroll 8
        for (int j = 0; j < DD; j++) {
            float w = Wg[i * DD + j];
            acc = fmaf(w, W1[j * DD + k], acc);
            accb = fmaf(w, b1[j], accb);
        }
        float h = __bfloat162float(__float2bfloat16(acc));
        int off = i * 256 + ((((k >> 3) ^ (i & 7))) << 4) + (k & 7) * 2;
        *(__nv_bfloat16*)((char*)g_Wfh + off) = __float2bfloat16(acc);
        *(__nv_bfloat16*)((char*)g_Wfl + off) = __float2bfloat16(acc - h);
        if (k == 0) g_bf[i] = accb;
    } else if (blockIdx.x < HBLK + 72) {
        int gidx = (blockIdx.x - HBLK - 64) * 256 + threadIdx.x;
        int r = gidx >> 4, g = gidx & 15;
        float4 u0 = *(const float4*)(W2 + (size_t)r * DD + g * 8);
        float4 u1 = *(const float4*)(W2 + (size_t)r * DD + g * 8 + 4);
        float v[8] = {u0.x, u0.y, u0.z, u0.w, u1.x, u1.y, u1.z, u1.w};
        uint32_t hi[4], lo[4];
#pragma unroll
        for (int p = 0; p < 4; p++) {
            float a0 = v[2 * p], a1 = v[2 * p + 1];
            float h0 = __bfloat162float(__float2bfloat16(a0));
            float h1 = __bfloat162float(__float2bfloat16(a1));
            hi[p] = pack_bf2(h0, h1);
            lo[p] = pack_bf2(a0 - h0, a1 - h1);
        }
        int off = r * 256 + (((g ^ (r & 7))) << 4);
        *(uint4*)((char*)g_W2h + off) = make_uint4(hi[0], hi[1], hi[2], hi[3]);
        *(uint4*)((char*)g_W2l + off) = make_uint4(lo[0], lo[1], lo[2], lo[3]);
    } else {
        int gidx = (blockIdx.x - HBLK - 72) * 256 + threadIdx.x;  // < NN*16
        int r = gidx >> 4, g = gidx & 15;
        float4 u0 = *(const float4*)(x + (size_t)r * DD + g * 8);
        float4 u1 = *(const float4*)(x + (size_t)r * DD + g * 8 + 4);
        float v[8] = {u0.x, u0.y, u0.z, u0.w, u1.x, u1.y, u1.z, u1.w};
#pragma unroll
        for (int i = 0; i < 8; i++) v[i] = lrelu(v[i], 0.01f);
        uint32_t hi[4], lo[4];
#pragma unroll
        for (int p = 0; p < 4; p++) {
            float a0 = v[2 * p], a1 = v[2 * p + 1];
            float h0 = __bfloat162float(__float2bfloat16(a0));
            float h1 = __bfloat162float(__float2bfloat16(a1));
            hi[p] = pack_bf2(h0, h1);
            lo[p] = pack_bf2(a0 - h0, a1 - h1);
        }
        size_t off = (size_t)r * 256 + ((g ^ (r & 7)) << 4);
        *(uint4*)((char*)g_xh + off) = make_uint4(hi[0], hi[1], hi[2], hi[3]);
        *(uint4*)((char*)g_xl + off) = make_uint4(lo[0], lo[1], lo[2], lo[3]);
    }
}

// ---------------------------------------------------------------------------
// HMMA GEMM, M-tile = 64 rows, 256 thr, 2 CTAs/SM (104 KB smem each):
// cross-CTA overlap hides staging latency (persistent version failed: serial).
// All operands pre-split bf16 hi/lo; staging = pure cp.async copy.
// Fragment reuse: aH feeds (aH*wH, aH*wL); wH feeds (aH*wH, aL*wH) ->
// 4x ldsm_x4 + 8x ldsm_x2 per k-step instead of 6/12 (L1 was the bottleneck).
// Warp grid 2(m)x4(n); per warp 2x4 m16n8 tiles.
// ATTN: CSR-scatter prologue; epilogue -> fp16 h mirror + attn scores.
// ---------------------------------------------------------------------------
template <bool ATTN>
__global__ void __launch_bounds__(256, 2) gemm_kernel(
    const uint4* __restrict__ Ah, const uint4* __restrict__ Al,
    const uint4* __restrict__ Wh, const uint4* __restrict__ Wl,
    const float* __restrict__ bias,
    const float* __restrict__ attS, const float* __restrict__ attD,
    float* __restrict__ out, int M, const int* __restrict__ ei)
{
    extern __shared__ char smem[];
    const int tid = threadIdx.x;
    const uint32_t sb = smem_u32(smem);
    const uint32_t sAh = sb, sAl = sb + 16384;
    const uint32_t sWh = sb + 32768, sWl = sb + 65536;
    float* sp = (float*)(smem + 98304);        // [64][16] (4 KB)
    float* sd = sp + 64 * 16;                  // [64][16] (4 KB)

    // ---- stage A subtile (64 rows = contiguous 1024 uint4 per half) ----
    const size_t aOff = (size_t)blockIdx.x * 1024;
#pragma unroll
    for (int it = 0; it < 4; it++) {
        int idx = tid + it * 256;  // 0..1023
        cp16(sAh + idx * 16, Ah + aOff + idx);
        cp16(sAl + idx * 16, Al + aOff + idx);
    }
    // ---- stage W (full 128x128, 2048 uint4 per half) ----
#pragma unroll
    for (int it = 0; it < 8; it++) {
        int idx = tid + it * 256;  // 0..2047
        cp16(sWh + idx * 16, Wh + idx);
        cp16(sWl + idx * 16, Wl + idx);
    }
    asm volatile("cp.async.commit_group;");

    if (ATTN) {  // CSR scatter overlaps the staging wait
        const int EPB = (EE + NT64 - 1) / NT64;  // 1024
        int e0 = blockIdx.x * EPB;
        int e1 = e0 + EPB < EE ? e0 + EPB : EE;
        for (int e = e0 + tid; e < e1; e += 256) {
            int src = ei[e];
            int dst = ei[EE + e];
            int pos = atomicAdd(&g_cur[dst], 1);
            g_csr_src[pos] = src;
        }
    }
    asm volatile("cp.async.wait_group 0;");
    __syncthreads();

    const int wid = tid >> 5, lane = tid & 31;
    const int wm = (wid >> 2) * 32, wn = (wid & 3) * 32;
    const int rowBase = blockIdx.x * 64;

    float D[2][4][4];
#pragma unroll
    for (int mt = 0; mt < 2; mt++)
#pragma unroll
        for (int nt = 0; nt < 4; nt++)
#pragma unroll
            for (int k = 0; k < 4; k++) D[mt][nt][k] = 0.f;

    const int subA = lane >> 3;
    const int rA = (lane & 7) | ((subA & 1) << 3);
    const int gA = subA >> 1;
    const int rB = lane & 7;
    const int gB = (lane >> 3) & 1;

#pragma unroll
    for (int ks = 0; ks < 8; ks++) {
        uint32_t aH[2][4], aL[2][4], bH[4][2], bL[4][2];
#pragma unroll
        for (int mt = 0; mt < 2; mt++) {
            int r = wm + mt * 16 + rA;
            int g = 2 * ks + gA;
            ldsm_x4(aH[mt][0], aH[mt][1], aH[mt][2], aH[mt][3],
                    sAh + r * 256 + ((g ^ (r & 7)) << 4));
        }
#pragma unroll
        for (int nt = 0; nt < 4; nt++) {
            int r = wn + nt * 8 + rB;
            int g = 2 * ks + gB;
            ldsm_x2(bH[nt][0], bH[nt][1],
                    sWh + r * 256 + ((g ^ (r & 7)) << 4));
        }
#pragma unroll
        for (int mt = 0; mt < 2; mt++)
#pragma unroll
            for (int nt = 0; nt < 4; nt++)
                mma16816(D[mt][nt], aH[mt], bH[nt]);     // Ah*Wh
#pragma unroll
        for (int nt = 0; nt < 4; nt++) {
            int r = wn + nt * 8 + rB;
            int g = 2 * ks + gB;
            ldsm_x2(bL[nt][0], bL[nt][1],
                    sWl + r * 256 + ((g ^ (r & 7)) << 4));
        }
#pragma unroll
        for (int mt = 0; mt < 2; mt++)
#pragma unroll
            for (int nt = 0; nt < 4; nt++)
                mma16816(D[mt][nt], aH[mt], bL[nt]);     // Ah*Wl
#pragma unroll
        for (int mt = 0; mt < 2; mt++) {
            int r = wm + mt * 16 + rA;
            int g = 2 * ks + gA;
            ldsm_x4(aL[mt][0], aL[mt][1], aL[mt][2], aL[mt][3],
                    sAl + r * 256 + ((g ^ (r & 7)) << 4));
        }
#pragma unroll
        for (int mt = 0; mt < 2; mt++)
#pragma unroll
            for (int nt = 0; nt < 4; nt++)
                mma16816(D[mt][nt], aL[mt], bH[nt]);     // Al*Wh
    }
    __syncthreads();  // tiles consumed; smem reusable for attention reduce

    // ---- epilogue ----
    const int q = lane >> 2, c2 = (lane & 3) * 2;
    float bj0[4], bj1[4], as0[4], as1[4], ad0[4], ad1[4];
#pragma unroll
    for (int nt = 0; nt < 4; nt++) {
        int col = wn + nt * 8 + c2;
        bj0[nt] = bias[col];
        bj1[nt] = bias[col + 1];
        if (ATTN) {
            as0[nt] = attS[col]; as1[nt] = attS[col + 1];
            ad0[nt] = attD[col]; ad1[nt] = attD[col + 1];
        }
    }

#pragma unroll
    for (int mt = 0; mt < 2; mt++) {
#pragma unroll
        for (int half = 0; half < 2; half++) {
            int rl = wm + mt * 16 + q + half * 8;
            int row = rowBase + rl;
            bool ok = row < M;
#pragma unroll
            for (int nt = 0; nt < 4; nt++) {
                int col = wn + nt * 8 + c2;
                float v0 = D[mt][nt][half * 2] + bj0[nt];
                float v1 = D[mt][nt][half * 2 + 1] + bj1[nt];
                if (ATTN) {
                    if (ok) {
                        *(__half2*)(g_h16 + (size_t)row * DD + col) =
                            __floats2half2_rn(v0, v1);
                    }
                    float ps = v0 * as0[nt] + v1 * as1[nt];
                    float pd = v0 * ad0[nt] + v1 * ad1[nt];
                    ps += __shfl_xor_sync(0xffffffffu, ps, 1);
                    ps += __shfl_xor_sync(0xffffffffu, ps, 2);
                    pd += __shfl_xor_sync(0xffffffffu, pd, 1);
                    pd += __shfl_xor_sync(0xffffffffu, pd, 2);
                    if ((lane & 3) == 0) {
                        sp[rl * 16 + (wid & 3) * 4 + nt] = ps;
                        sd[rl * 16 + (wid & 3) * 4 + nt] = pd;
                    }
                } else if (ok) {
                    *(float2*)(out + (size_t)row * DD + col) =
                        make_float2(v0, v1);
                }
            }
        }
    }
    if (ATTN) {
        __syncthreads();
        if (tid < 64) {
            int row = rowBase + tid;
            if (row < M) {
#pragma unroll
                for (int h = 0; h < 4; h++) {
                    float s = sp[tid * 16 + h * 4 + 0] + sp[tid * 16 + h * 4 + 1]
                            + sp[tid * 16 + h * 4 + 2] + sp[tid * 16 + h * 4 + 3];
                    float d = sd[tid * 16 + h * 4 + 0] + sd[tid * 16 + h * 4 + 1]
                            + sd[tid * 16 + h * 4 + 2] + sd[tid * 16 + h * 4 + 3];
                    g_asrc[row * HH + h] = s;
                    g_adst[row * HH + h] = d;
                }
            }
        }
    }
}

// -------------------------- CSR scan + cursor copy ------------------------
__global__ void __launch_bounds__(1024) scan_kernel() {
    __shared__ int ssum[1024];
    const int t = threadIdx.x;
    const int CH = (NN + 1023) / 1024;
    const int base = t * CH;

    int s = 0;
#pragma unroll 4
    for (int i = 0; i < CH; i++) {
        int idx = base + i;
        if (idx < NN) s += g_cnt[idx];
    }
    ssum[t] = s;
    __syncthreads();
    for (int off = 1; off < 1024; off <<= 1) {
        int v = ssum[t];
        int add = (t >= off) ? ssum[t - off] : 0;
        __syncthreads();
        ssum[t] = v + add;
        __syncthreads();
    }
    int run = ssum[t] - s;
    for (int i = 0; i < CH; i++) {
        int idx = base + i;
        if (idx < NN) {
            g_off[idx] = run;
            run += g_cnt[idx];
        }
    }
    if (t == 1023) g_off[NN] = EE;
}

__global__ void __launch_bounds__(256) cur_copy_kernel() {
    int idx = blockIdx.x * 256 + threadIdx.x;
    if (idx < NN) g_cur[idx] = g_off[idx];
}

// ---------------------------------------------------------------------------
// Fused softmax + aggregation: warp per dst; fp16 gathers. Applies +bias_g
// and leaky, writes bf16 hi/lo directly into gemm<0>'s tile layout.
// Zeroes g_cnt for next call.
// ---------------------------------------------------------------------------
__global__ void __launch_bounds__(256) agg_kernel(const float* __restrict__ bg) {
    int warp = (blockIdx.x * blockDim.x + threadIdx.x) >> 5;
    int lane = threadIdx.x & 31;
    if (warp >= NN) return;
    const int d = warp;
    const int head = lane >> 3;
    const int ph = lane & 3;
    const int pe = lane >> 2;
    const int beg = g_off[d], end = g_off[d + 1];
    const float adst_ph = g_adst[d * HH + ph];
    const float4 bgl = *(const float4*)(bg + lane * 4);

    if (lane == 0) g_cnt[d] = 0;

    float4 acc = make_float4(0.f, 0.f, 0.f, 0.f);
    float den = 0.f;

    int base = beg;
    for (; base + 8 <= end; base += 8) {
        int srcl = g_csr_src[base + pe];
        float s = g_asrc[srcl * HH + ph] + adst_ph;
        float exv = __expf(lrelu(s, 0.2f));
#pragma unroll
        for (int j = 0; j < 8; j++) {
            float ex = __shfl_sync(0xffffffffu, exv, j * 4 + head);
            int sj = __shfl_sync(0xffffffffu, srcl, j * 4 + head);
            uint2 u = *(const uint2*)(g_h16 + (size_t)sj * DD + lane * 4);
            float2 f0 = __half22float2(*(__half2*)&u.x);
            float2 f1 = __half22float2(*(__half2*)&u.y);
            acc.x = fmaf(ex, f0.x, acc.x);
            acc.y = fmaf(ex, f0.y, acc.y);
            acc.z = fmaf(ex, f1.x, acc.z);
            acc.w = fmaf(ex, f1.y, acc.w);
            den += ex;
        }
    }
    if (base < end) {
        int eidx = base + pe;
        int srcl = 0;
        float exv = 0.f;
        if (eidx < end) {
            srcl = g_csr_src[eidx];
            float s = g_asrc[srcl * HH + ph] + adst_ph;
            exv = __expf(lrelu(s, 0.2f));
        }
        int nrem = end - base;
#pragma unroll
        for (int j = 0; j < 8; j++) {
            if (j >= nrem) break;
            float ex = __shfl_sync(0xffffffffu, exv, j * 4 + head);
            int sj = __shfl_sync(0xffffffffu, srcl, j * 4 + head);
            uint2 u = *(const uint2*)(g_h16 + (size_t)sj * DD + lane * 4);
            float2 f0 = __half22float2(*(__half2*)&u.x);
            float2 f1 = __half22float2(*(__half2*)&u.y);
            acc.x = fmaf(ex, f0.x, acc.x);
            acc.y = fmaf(ex, f0.y, acc.y);
            acc.z = fmaf(ex, f1.x, acc.z);
            acc.w = fmaf(ex, f1.y, acc.w);
            den += ex;
        }
    }
    float inv = 1.f / (den + 1e-16f);
    float v[4] = {lrelu(acc.x * inv + bgl.x, 0.01f),
                  lrelu(acc.y * inv + bgl.y, 0.01f),
                  lrelu(acc.z * inv + bgl.z, 0.01f),
                  lrelu(acc.w * inv + bgl.w, 0.01f)};
    float h0 = __bfloat162float(__float2bfloat16(v[0]));
    float h1 = __bfloat162float(__float2bfloat16(v[1]));
    float h2 = __bfloat162float(__float2bfloat16(v[2]));
    float h3 = __bfloat162float(__float2bfloat16(v[3]));
    uint2 hi = make_uint2(pack_bf2(h0, h1), pack_bf2(h2, h3));
    uint2 lo = make_uint2(pack_bf2(v[0] - h0, v[1] - h1),
                          pack_bf2(v[2] - h2, v[3] - h3));
    size_t off = (size_t)d * 256 + (((lane >> 1) ^ (d & 7)) << 4) + (lane & 1) * 8;
    *(uint2*)((char*)g_ah + off) = hi;
    *(uint2*)((char*)g_al + off) = lo;
}

// ---------------------------------------------------------------------------
extern "C" void kernel_launch(void* const* d_in, const int* in_sizes, int n_in,
                              void* d_out, int out_size) {
    const float* x       = (const float*)d_in[0];
    const int*   ei      = (const int*)d_in[1];
    // d_in[2] = edge_type (unused by forward)
    const float* W1      = (const float*)d_in[3];
    const float* b1      = (const float*)d_in[4];
    const float* Wg      = (const float*)d_in[5];
    const float* att_src = (const float*)d_in[6];
    const float* att_dst = (const float*)d_in[7];
    const float* bias_g  = (const float*)d_in[8];
    const float* W2      = (const float*)d_in[9];
    const float* b2      = (const float*)d_in[10];
    float* out = (float*)d_out;

    float *pbf;
    uint4 *pWfh, *pWfl, *pW2h, *pW2l, *pxh, *pxl, *pah, *pal;
    cudaGetSymbolAddress((void**)&pbf, g_bf);
    cudaGetSymbolAddress((void**)&pWfh, g_Wfh);
    cudaGetSymbolAddress((void**)&pWfl, g_Wfl);
    cudaGetSymbolAddress((void**)&pW2h, g_W2h);
    cudaGetSymbolAddress((void**)&pW2l, g_W2l);
    cudaGetSymbolAddress((void**)&pxh, g_xh);
    cudaGetSymbolAddress((void**)&pxl, g_xl);
    cudaGetSymbolAddress((void**)&pah, g_ah);
    cudaGetSymbolAddress((void**)&pal, g_al);

    const int SMEM = 104 * 1024;  // A(32K) W(64K) sp(4K) sd(4K) -> 2 CTAs/SM
    cudaFuncSetAttribute(gemm_kernel<true>,
                         cudaFuncAttributeMaxDynamicSharedMemorySize, SMEM);
    cudaFuncSetAttribute(gemm_kernel<false>,
                         cudaFuncAttributeMaxDynamicSharedMemorySize, SMEM);

    // 1: histogram + Wf/bf + W2 split + x split (fused grid)
    setup_kernel<<<HBLK + 72 + XBLK, 256>>>(ei, Wg, W1, b1, W2, x);
    // 2: CSR offsets
    scan_kernel<<<1, 1024>>>();
    // 3: cursor copy
    cur_copy_kernel<<<(NN + 255) / 256, 256>>>();
    // 4: scatter + h16/attn GEMM, 64-row tiles, 2 CTAs/SM (<- profiled)
    gemm_kernel<true><<<NT64, 256, SMEM>>>(pxh, pxl, pWfh, pWfl, pbf,
                                           att_src, att_dst, nullptr, NN, ei);
    // 5: fused softmax + aggregation (writes pre-split bf16 tiles)
    agg_kernel<<<(NN * 32 + 255) / 256, 256>>>(bias_g);
    // 6: out = agg16 @ W2^T + b2
    gemm_kernel<false><<<NT64, 256, SMEM>>>(pah, pal, pW2h, pW2l, b2,
                                            nullptr, nullptr, out, NN, nullptr);
}